// round 3
// baseline (speedup 1.0000x reference)
#include <cuda_runtime.h>

// Problem constants (fixed shapes per reference)
#define BB   16
#define NN   1024
#define D2H  1024
#define UU   512
#define BN   (BB * NN)   // 16384 rows

// Scratch (device globals; no allocation allowed)
__device__ float g_v[2 * D2H];   // [0:1024) = v_h, [1024:2048) = v_m
__device__ float g_c[2];         // c_h + b_out, c_m
__device__ float g_sH[BN];
__device__ float g_sM[BN];

// ---------------------------------------------------------------------------
// Kernel 1: fold the output layer into the input space.
//   v_h[d] = sum_u W_h[u,d] * w_out[u]   (coalesced over d)
//   c_h    = w_out . b_h  (+ b_out folded into c_h)
// Grid: 4 blocks x 256 threads (one thread per d).
// ---------------------------------------------------------------------------
__global__ void fold_kernel(const float* __restrict__ W_h,
                            const float* __restrict__ b_h,
                            const float* __restrict__ W_m,
                            const float* __restrict__ b_m,
                            const float* __restrict__ w_out,
                            const float* __restrict__ b_out) {
    __shared__ float sw[UU];
    int tid = threadIdx.x;
    for (int i = tid; i < UU; i += blockDim.x) sw[i] = w_out[i];
    __syncthreads();

    int d = blockIdx.x * blockDim.x + tid;
    float vh = 0.f, vm = 0.f;
#pragma unroll 8
    for (int u = 0; u < UU; u++) {
        float w = sw[u];
        vh = fmaf(W_h[u * D2H + d], w, vh);
        vm = fmaf(W_m[u * D2H + d], w, vm);
    }
    g_v[d]       = vh;
    g_v[D2H + d] = vm;

    if (blockIdx.x == 0 && tid < 32) {
        float ch = 0.f, cm = 0.f;
        for (int u = tid; u < UU; u += 32) {
            ch = fmaf(b_h[u], sw[u], ch);
            cm = fmaf(b_m[u], sw[u], cm);
        }
#pragma unroll
        for (int o = 16; o > 0; o >>= 1) {
            ch += __shfl_down_sync(0xffffffffu, ch, o);
            cm += __shfl_down_sync(0xffffffffu, cm, o);
        }
        if (tid == 0) {
            g_c[0] = ch + b_out[0];
            g_c[1] = cm;
        }
    }
}

// ---------------------------------------------------------------------------
// Kernel 2: one pass over x computing both dot products per row.
//   sH[r] = x[r,:] . v_h + c_h + b_out ;  sM[r] = x[r,:] . v_m + c_m
// Warp-per-row, float4 loads, 8 outstanding loads per lane.
// Grid: 4096 blocks x 128 threads (4 warps/block).
// ---------------------------------------------------------------------------
__global__ void dots_kernel(const float* __restrict__ x) {
    __shared__ float4 sv[2 * D2H / 4];   // 8 KB: v_h then v_m as float4
    int tid = threadIdx.x;
    const float4* gv4 = (const float4*)g_v;
    for (int i = tid; i < 2 * D2H / 4; i += 128) sv[i] = gv4[i];
    __syncthreads();

    int warp = tid >> 5, lane = tid & 31;
    int row  = blockIdx.x * 4 + warp;

    const float4* x4 = (const float4*)(x + (size_t)row * D2H);
    float ah = 0.f, am = 0.f;
#pragma unroll
    for (int k = 0; k < 8; k++) {
        int i = k * 32 + lane;           // 256 float4 per row, coalesced
        float4 v = x4[i];
        float4 h = sv[i];
        float4 m = sv[256 + i];
        ah = fmaf(v.x, h.x, fmaf(v.y, h.y, fmaf(v.z, h.z, fmaf(v.w, h.w, ah))));
        am = fmaf(v.x, m.x, fmaf(v.y, m.y, fmaf(v.z, m.z, fmaf(v.w, m.w, am))));
    }
#pragma unroll
    for (int o = 16; o > 0; o >>= 1) {
        ah += __shfl_down_sync(0xffffffffu, ah, o);
        am += __shfl_down_sync(0xffffffffu, am, o);
    }
    if (lane == 0) {
        g_sH[row] = ah + g_c[0];
        g_sM[row] = am + g_c[1];
    }
}

// ---------------------------------------------------------------------------
// Kernel 3: broadcast-add to the [B,N,N] output.
//   out[b,i,j] = sH[b*N+i] + sM[b*N+j]
// Block per (b,i) row; 256 threads write one float4 each (4 KB/row).
// sM rows (4 KB/batch) stay hot in L2.
// ---------------------------------------------------------------------------
__global__ void bcast_kernel(float* __restrict__ out) {
    int bi = blockIdx.x;          // 0 .. 16383  == b*N + i
    int b  = bi >> 10;            // N = 1024
    float s = g_sH[bi];
    const float4* m4 = (const float4*)g_sM + b * (NN / 4);
    float4 m = m4[threadIdx.x];
    float4 r = make_float4(s + m.x, s + m.y, s + m.z, s + m.w);
    ((float4*)out)[(size_t)bi * (NN / 4) + threadIdx.x] = r;
}

// ---------------------------------------------------------------------------
extern "C" void kernel_launch(void* const* d_in, const int* in_sizes, int n_in,
                              void* d_out, int out_size) {
    const float* x     = (const float*)d_in[0];
    const float* W_h   = (const float*)d_in[1];
    const float* b_h   = (const float*)d_in[2];
    const float* W_m   = (const float*)d_in[3];
    const float* b_m   = (const float*)d_in[4];
    const float* w_out = (const float*)d_in[5];
    const float* b_out = (const float*)d_in[6];
    float* out = (float*)d_out;

    fold_kernel<<<D2H / 256, 256>>>(W_h, b_h, W_m, b_m, w_out, b_out);
    dots_kernel<<<BN / 4, 128>>>(x);
    bcast_kernel<<<BN, 256>>>(out);
}

// round 4
// speedup vs baseline: 2.4455x; 2.4455x over previous
#include <cuda_runtime.h>

// Problem constants (fixed shapes per reference)
#define BB   16
#define NN   1024
#define D2H  1024
#define UU   512
#define BN   (BB * NN)      // 16384 rows

#define UCHUNKS 32          // u split for the fold reduction
#define UC_SZ   (UU / UCHUNKS)   // 16 u per chunk

// Scratch (device globals; no allocation allowed)
__device__ float g_part[UCHUNKS * 2 * D2H];  // partial v_h/v_m per u-chunk (256 KB)
__device__ float g_v[2 * D2H];               // [0:1024)=v_h, [1024:2048)=v_m
__device__ float g_c[2];                     // c_h + b_out, c_m
__device__ float g_sH[BN];
__device__ float g_sM[BN];

// ---------------------------------------------------------------------------
// Kernel 1: partial fold. v_h[d] = sum_u W_h[u,d]*w_out[u], split over UCHUNKS.
// Grid: 128 blocks (32 u-chunks x 4 d-blocks) x 256 threads. Each thread does
// 16+16 coalesced loads -> massive MLP, ~2us for the 4MB of weights.
// ---------------------------------------------------------------------------
__global__ void fold_part_kernel(const float* __restrict__ W_h,
                                 const float* __restrict__ W_m,
                                 const float* __restrict__ w_out) {
    __shared__ float sw[UC_SZ];
    int tid = threadIdx.x;
    int uc  = blockIdx.x >> 2;           // u-chunk
    int db  = blockIdx.x & 3;            // d-block
    int u0  = uc * UC_SZ;
    if (tid < UC_SZ) sw[tid] = w_out[u0 + tid];
    __syncthreads();

    int d = db * 256 + tid;
    float vh = 0.f, vm = 0.f;
#pragma unroll
    for (int k = 0; k < UC_SZ; k++) {
        int u = u0 + k;
        vh = fmaf(W_h[u * D2H + d], sw[k], vh);
        vm = fmaf(W_m[u * D2H + d], sw[k], vm);
    }
    g_part[uc * 2 * D2H + d]       = vh;
    g_part[uc * 2 * D2H + D2H + d] = vm;
}

// ---------------------------------------------------------------------------
// Kernel 2: reduce partials into g_v, and compute the bias constants.
// Grid: 2 blocks x 1024 threads. 256 KB L2-resident read, ~1us.
// ---------------------------------------------------------------------------
__global__ void reduce_kernel(const float* __restrict__ b_h,
                              const float* __restrict__ b_m,
                              const float* __restrict__ w_out,
                              const float* __restrict__ b_out) {
    int idx = blockIdx.x * 1024 + threadIdx.x;   // 0 .. 2047
    float acc = 0.f;
#pragma unroll
    for (int c = 0; c < UCHUNKS; c++)
        acc += g_part[c * 2 * D2H + idx];
    g_v[idx] = acc;

    if (blockIdx.x == 0 && threadIdx.x < 32) {
        int lane = threadIdx.x;
        float ch = 0.f, cm = 0.f;
        for (int u = lane; u < UU; u += 32) {
            float w = w_out[u];
            ch = fmaf(b_h[u], w, ch);
            cm = fmaf(b_m[u], w, cm);
        }
#pragma unroll
        for (int o = 16; o > 0; o >>= 1) {
            ch += __shfl_down_sync(0xffffffffu, ch, o);
            cm += __shfl_down_sync(0xffffffffu, cm, o);
        }
        if (lane == 0) {
            g_c[0] = ch + b_out[0];
            g_c[1] = cm;
        }
    }
}

// ---------------------------------------------------------------------------
// Kernel 3: one pass over x computing both dot products per row.
//   sH[r] = x[r,:].v_h + c_h(+b_out) ;  sM[r] = x[r,:].v_m + c_m
// Warp-per-row, float4 loads. 256 threads (8 rows/block) to amortize the
// g_v -> smem stage. Grid: 2048 blocks.
// ---------------------------------------------------------------------------
__global__ void dots_kernel(const float* __restrict__ x) {
    __shared__ float4 sv[2 * D2H / 4];   // 8 KB: v_h then v_m as float4
    int tid = threadIdx.x;
    const float4* gv4 = (const float4*)g_v;
    for (int i = tid; i < 2 * D2H / 4; i += 256) sv[i] = gv4[i];
    __syncthreads();

    int warp = tid >> 5, lane = tid & 31;
    int row  = blockIdx.x * 8 + warp;

    const float4* x4 = (const float4*)(x + (size_t)row * D2H);
    float ah = 0.f, am = 0.f;
#pragma unroll
    for (int k = 0; k < 8; k++) {
        int i = k * 32 + lane;           // 256 float4 per row, coalesced
        float4 v = x4[i];
        float4 h = sv[i];
        float4 m = sv[256 + i];
        ah = fmaf(v.x, h.x, fmaf(v.y, h.y, fmaf(v.z, h.z, fmaf(v.w, h.w, ah))));
        am = fmaf(v.x, m.x, fmaf(v.y, m.y, fmaf(v.z, m.z, fmaf(v.w, m.w, am))));
    }
#pragma unroll
    for (int o = 16; o > 0; o >>= 1) {
        ah += __shfl_down_sync(0xffffffffu, ah, o);
        am += __shfl_down_sync(0xffffffffu, am, o);
    }
    if (lane == 0) {
        g_sH[row] = ah + g_c[0];
        g_sM[row] = am + g_c[1];
    }
}

// ---------------------------------------------------------------------------
// Kernel 4: broadcast-add to the [B,N,N] output.
//   out[b,i,j] = sH[b*N+i] + sM[b*N+j]
// 4 output rows per block (same batch: 4 | 1024); each thread holds one
// float4 of sM in registers and writes it into 4 rows -> 4x less L2 re-read.
// Grid: 4096 blocks x 256 threads.
// ---------------------------------------------------------------------------
__global__ void bcast_kernel(float* __restrict__ out) {
    int bi0 = blockIdx.x * 4;            // first of 4 consecutive (b,i) rows
    int b   = bi0 >> 10;                 // N = 1024
    const float4* m4 = (const float4*)g_sM + b * (NN / 4);
    float4 m = m4[threadIdx.x];

    float s0 = g_sH[bi0 + 0];
    float s1 = g_sH[bi0 + 1];
    float s2 = g_sH[bi0 + 2];
    float s3 = g_sH[bi0 + 3];

    float4* o4 = (float4*)out + (size_t)bi0 * (NN / 4) + threadIdx.x;
    o4[0 * (NN / 4)] = make_float4(s0 + m.x, s0 + m.y, s0 + m.z, s0 + m.w);
    o4[1 * (NN / 4)] = make_float4(s1 + m.x, s1 + m.y, s1 + m.z, s1 + m.w);
    o4[2 * (NN / 4)] = make_float4(s2 + m.x, s2 + m.y, s2 + m.z, s2 + m.w);
    o4[3 * (NN / 4)] = make_float4(s3 + m.x, s3 + m.y, s3 + m.z, s3 + m.w);
}

// ---------------------------------------------------------------------------
extern "C" void kernel_launch(void* const* d_in, const int* in_sizes, int n_in,
                              void* d_out, int out_size) {
    const float* x     = (const float*)d_in[0];
    const float* W_h   = (const float*)d_in[1];
    const float* b_h   = (const float*)d_in[2];
    const float* W_m   = (const float*)d_in[3];
    const float* b_m   = (const float*)d_in[4];
    const float* w_out = (const float*)d_in[5];
    const float* b_out = (const float*)d_in[6];
    float* out = (float*)d_out;

    fold_part_kernel<<<UCHUNKS * 4, 256>>>(W_h, W_m, w_out);
    reduce_kernel<<<2, 1024>>>(b_h, b_m, w_out, b_out);
    dots_kernel<<<BN / 8, 256>>>(x);
    bcast_kernel<<<BN / 4, 256>>>(out);
}